// round 5
// baseline (speedup 1.0000x reference)
#include <cuda_runtime.h>

#define BB 2
#define NN 1024
#define CC 256
#define PP 256
#define KPP 27
#define NS 16
#define H1 128
#define H2 64
#define H3 32
#define MTOT (H3*KPP)          // 864
#define RADIUS 0.2f
#define KP_PER_B (PP*KPP)      // 6912
#define KP_TOTAL (BB*KP_PER_B) // 13824
#define SMAX (KP_TOTAL*NS)     // 221184

// ---- scratch ----
__device__ float g_F1[BB*NN*H1];       // feat @ W1[3:] + b1 (split-K accum)
__device__ float g_kpts[KP_TOTAL*3];
__device__ int   g_slist[SMAX];        // packed (g<<10)|n
__device__ int   g_scount;
__device__ float g_pool[BB*PP*H3*KPP]; // [b][p][c][k], atomicMax'd as int bits

// ============================================================
// K0: init — scount=0, pool=0, F1=b1, out=br
// grid = 1728 x 256 (covers 442368)
// ============================================================
__global__ void k0_prep(const float* __restrict__ b1,
                        const float* __restrict__ br,
                        float* __restrict__ out) {
    int i = blockIdx.x * blockDim.x + threadIdx.x;
    if (i == 0) g_scount = 0;
    if (i < BB*H1*PP)           out[i] = br[(i >> 8) & 127];
    if (i < BB*NN*H1)           g_F1[i] = b1[i & 127];
    if (i < BB*PP*H3*KPP)       ((int*)g_pool)[i] = 0;
}

// ============================================================
// K1: F1 += feat^T @ W1[3:], split-K=4 (64 c per block)
// grid = 2b * 16nt * 2jt * 4kc = 256 blocks x 256
// ============================================================
__global__ void k1_f1(const float* __restrict__ feat,
                      const float* __restrict__ W1) {
    __shared__ __align__(16) float As[32][64];
    __shared__ __align__(16) float Bs[32][64];
    int bx = blockIdx.x;
    int kc = bx & 3;
    int jt = (bx >> 2) & 1;
    int nt = (bx >> 3) & 15;
    int b  = bx >> 7;
    int n0 = nt * 64, j0 = jt * 64, cbase = kc * 64;
    int t  = threadIdx.x;
    int tr = t >> 4, tc = t & 15;
    float acc[4][4] = {};
    float ra[8], rb[8];

    const float* fb = feat + (size_t)b*CC*NN;
#pragma unroll
    for (int i = 0; i < 8; i++) {
        int e = t + 256*i; int cc = e >> 6, nn = e & 63;
        ra[i] = fb[(size_t)(cbase+cc)*NN + n0 + nn];
        rb[i] = W1[(size_t)(3 + cbase + cc)*H1 + j0 + nn];
    }
#pragma unroll
    for (int c0 = 0; c0 < 64; c0 += 32) {
        __syncthreads();
#pragma unroll
        for (int i = 0; i < 8; i++) {
            int e = t + 256*i; int cc = e >> 6, nn = e & 63;
            As[cc][nn] = ra[i];
            Bs[cc][nn] = rb[i];
        }
        __syncthreads();
        if (c0 == 0) {
#pragma unroll
            for (int i = 0; i < 8; i++) {
                int e = t + 256*i; int cc = e >> 6, nn = e & 63;
                ra[i] = fb[(size_t)(cbase+32+cc)*NN + n0 + nn];
                rb[i] = W1[(size_t)(3 + cbase+32+cc)*H1 + j0 + nn];
            }
        }
#pragma unroll
        for (int kk = 0; kk < 32; kk++) {
            float4 a = *(const float4*)&As[kk][tr*4];
            float4 w = *(const float4*)&Bs[kk][tc*4];
            float av[4] = {a.x,a.y,a.z,a.w};
            float wv[4] = {w.x,w.y,w.z,w.w};
#pragma unroll
            for (int r = 0; r < 4; r++)
#pragma unroll
                for (int q = 0; q < 4; q++) acc[r][q] += av[r]*wv[q];
        }
    }
#pragma unroll
    for (int r = 0; r < 4; r++) {
        int n = n0 + tr*4 + r;
#pragma unroll
        for (int q = 0; q < 4; q++) {
            int j = j0 + tc*4 + q;
            atomicAdd(&g_F1[((size_t)b*NN + n)*H1 + j], acc[r][q]);
        }
    }
}

// ============================================================
// K2: keypoints + ball query + APPEND compacted sample list
// warp/keypoint, 8 warps/block, grid = KP_TOTAL/8 = 1728
// ============================================================
__global__ void k2_ballquery(const float* __restrict__ seed_xyz,
                             const float* __restrict__ boxes,
                             const float* __restrict__ origins,
                             const float* __restrict__ heading) {
    __shared__ float sx[NN], sy[NN], sz[NN], ssq[NN];
    __shared__ int sbuf[8][16];
    int b      = blockIdx.x / (KP_PER_B / 8);
    int kpbase = (blockIdx.x % (KP_PER_B / 8)) * 8;
    int t = threadIdx.x;
    for (int i = t; i < NN; i += 256) {
        float x = seed_xyz[((size_t)b*NN + i)*3 + 0];
        float y = seed_xyz[((size_t)b*NN + i)*3 + 1];
        float z = seed_xyz[((size_t)b*NN + i)*3 + 2];
        sx[i]=x; sy[i]=y; sz[i]=z; ssq[i]=x*x+y*y+z*z;
    }
    __syncthreads();

    int w = t >> 5, lane = t & 31;
    int kpid = kpbase + w;
    int g = b*KP_PER_B + kpid;
    int p = kpid / KPP, k = kpid % KPP;

    const float* bx = boxes + ((size_t)b*PP + p)*6;
    float b0=bx[0], b1v=bx[1], b2v=bx[2], b3v=bx[3], b4v=bx[4], b5v=bx[5];
    const float* og = origins + ((size_t)b*PP + p)*3;
    float h = heading[(size_t)b*PP + p];
    int i0 = k/9, i1 = (k/3)%3, i2 = k%3;
    float lx = (i0+0.5f)/3.0f*(b0+b3v) - b0;
    float ly = (i1+0.5f)/3.0f*(b1v+b4v) - b1v;
    float lz = (i2+0.5f)/3.0f*(b2v+b5v) - b2v;
    float ch = cosf(h), sh = sinf(h);
    float px =  lx*ch + ly*sh + og[0];
    float py = -lx*sh + ly*ch + og[1];
    float pz =  lz + og[2];

    float kn2 = px*px + py*py + pz*pz;
    const float r2 = RADIUS*RADIUS;
    unsigned total = 0;
    for (int base = 0; base < NN; base += 32) {
        int n = base + lane;
        float d2 = kn2 + ssq[n] - 2.0f*(px*sx[n] + py*sy[n] + pz*sz[n]);
        bool in = d2 < r2;
        unsigned m = __ballot_sync(0xffffffffu, in);
        if (m && total < 16u) {
            int before = __popc(m & ((1u << lane) - 1u));
            if (in && total + before < 16u)
                sbuf[w][total + before] = n;
        }
        total += __popc(m);
        if (total >= 16u) break;
    }
    __syncwarp();
    int stored = total < 16u ? (int)total : 16;
    int emit = stored == 0 ? 1 : stored;   // empty -> reference fill with seed 0
    int base = 0;
    if (lane == 0) base = atomicAdd(&g_scount, emit);
    base = __shfl_sync(0xffffffffu, base, 0);
    if (lane < emit) {
        int n = (stored == 0) ? 0 : sbuf[w][lane];
        g_slist[base + lane] = (g << 10) | n;
    }
    if (lane == 0) {
        g_kpts[g*3+0] = px; g_kpts[g*3+1] = py; g_kpts[g*3+2] = pz;
    }
}

// ============================================================
// K3: persistent batched MLP over compacted samples.
// Tile = 32 samples: gather h1 -> GEMM(32x128x64) -> GEMM(32x64x32)
// -> atomicMax(int bits) into pool. grid = 592 x 256
// ============================================================
__global__ void k3_gemm(const float* __restrict__ seed_xyz,
                        const float* __restrict__ W1,
                        const float* __restrict__ W2,
                        const float* __restrict__ b2,
                        const float* __restrict__ W3,
                        const float* __restrict__ b3) {
    __shared__ float h1T[H1][33];   // [j][s]
    __shared__ float h2T[H2][33];   // [o][s]
    __shared__ __align__(16) float Wc[64][64];
    __shared__ float w1s[3][H1];
    __shared__ float sm_gx[32], sm_gy[32], sm_gz[32];
    __shared__ int   sm_f1[32], sm_pb[32];
    int t = threadIdx.x;
    if (t < 128) {
        w1s[0][t] = W1[t];
        w1s[1][t] = W1[128 + t];
        w1s[2][t] = W1[256 + t];
    }
    int count  = g_scount;
    int ntiles = (count + 31) >> 5;

    for (int tile = blockIdx.x; tile < ntiles; tile += gridDim.x) {
        __syncthreads();
        if (t < 32) {
            int pos = tile*32 + t;
            if (pos >= count) pos = count - 1;   // dup of last: idempotent under max
            int e = g_slist[pos];
            int g = e >> 10, n = e & 1023;
            int b = g / KP_PER_B;
            int rem = g % KP_PER_B;
            int p = rem / KPP, kk = rem % KPP;
            sm_pb[t] = ((b*PP + p)*H3)*KPP + kk;
            int sidx = b*NN + n;
            sm_f1[t] = sidx;
            const float* sp = seed_xyz + (size_t)sidx*3;
            sm_gx[t] = (sp[0] - g_kpts[g*3+0]) * 5.0f;
            sm_gy[t] = (sp[1] - g_kpts[g*3+1]) * 5.0f;
            sm_gz[t] = (sp[2] - g_kpts[g*3+2]) * 5.0f;
        }
        __syncthreads();
        // --- h1 gather: thread (s = t/8, u = t%8) covers j = u*16..u*16+15
        {
            int s = t >> 3, u = t & 7;
            const float* f1 = g_F1 + (size_t)sm_f1[s]*H1;
            float gx = sm_gx[s], gy = sm_gy[s], gz = sm_gz[s];
#pragma unroll
            for (int q = 0; q < 4; q++) {
                int j = u*16 + q*4;
                float4 f = __ldg((const float4*)&f1[j]);
                h1T[j+0][s] = fmaxf(f.x + gx*w1s[0][j+0] + gy*w1s[1][j+0] + gz*w1s[2][j+0], 0.f);
                h1T[j+1][s] = fmaxf(f.y + gx*w1s[0][j+1] + gy*w1s[1][j+1] + gz*w1s[2][j+1], 0.f);
                h1T[j+2][s] = fmaxf(f.z + gx*w1s[0][j+2] + gy*w1s[1][j+2] + gz*w1s[2][j+2], 0.f);
                h1T[j+3][s] = fmaxf(f.w + gx*w1s[0][j+3] + gy*w1s[1][j+3] + gz*w1s[2][j+3], 0.f);
            }
        }
        // --- GEMM1: h2[s][o] ; thread: samples {s0,s0+16}, outputs o0..o0+3
        int s0 = t & 15, og = t >> 4, o0 = og * 4;
        float4 bb = __ldg((const float4*)&b2[o0]);
        float acc0[4] = {bb.x, bb.y, bb.z, bb.w};
        float acc1[4] = {bb.x, bb.y, bb.z, bb.w};
#pragma unroll
        for (int c = 0; c < 2; c++) {
            __syncthreads();
#pragma unroll
            for (int q = 0; q < 4; q++) {
                int fi = t + 256*q;
                int r = fi >> 4, c4 = (fi & 15) * 4;
                *(float4*)&Wc[r][c4] = __ldg((const float4*)&W2[(size_t)(c*64 + r)*H2 + c4]);
            }
            __syncthreads();
#pragma unroll
            for (int k = 0; k < 64; k++) {
                float a0 = h1T[c*64 + k][s0];
                float a1 = h1T[c*64 + k][s0 + 16];
                float4 wv = *(const float4*)&Wc[k][o0];
                acc0[0] = fmaf(a0, wv.x, acc0[0]); acc0[1] = fmaf(a0, wv.y, acc0[1]);
                acc0[2] = fmaf(a0, wv.z, acc0[2]); acc0[3] = fmaf(a0, wv.w, acc0[3]);
                acc1[0] = fmaf(a1, wv.x, acc1[0]); acc1[1] = fmaf(a1, wv.y, acc1[1]);
                acc1[2] = fmaf(a1, wv.z, acc1[2]); acc1[3] = fmaf(a1, wv.w, acc1[3]);
            }
        }
        __syncthreads();
#pragma unroll
        for (int q = 0; q < 4; q++) {
            h2T[o0+q][s0]      = fmaxf(acc0[q], 0.f);
            h2T[o0+q][s0 + 16] = fmaxf(acc1[q], 0.f);
        }
        __syncthreads();
        // --- GEMM2: out[s][c] ; thread: sample s = t&31, channels cg*4..+3
        {
            int s = t & 31, cg = t >> 5;
            float4 b3v = __ldg((const float4*)&b3[cg*4]);
            float a0 = b3v.x, a1 = b3v.y, a2 = b3v.z, a3 = b3v.w;
#pragma unroll
            for (int k = 0; k < 64; k++) {
                float hv = h2T[k][s];
                float4 wv = __ldg((const float4*)&W3[(size_t)k*H3 + cg*4]);
                a0 = fmaf(hv, wv.x, a0); a1 = fmaf(hv, wv.y, a1);
                a2 = fmaf(hv, wv.z, a2); a3 = fmaf(hv, wv.w, a3);
            }
            int pb = sm_pb[s];
            int* pool = (int*)g_pool;
            atomicMax(&pool[pb + (cg*4+0)*KPP], __float_as_int(fmaxf(a0, 0.f)));
            atomicMax(&pool[pb + (cg*4+1)*KPP], __float_as_int(fmaxf(a1, 0.f)));
            atomicMax(&pool[pb + (cg*4+2)*KPP], __float_as_int(fmaxf(a2, 0.f)));
            atomicMax(&pool[pb + (cg*4+3)*KPP], __float_as_int(fmaxf(a3, 0.f)));
        }
    }
}

// ============================================================
// K4: out += pool @ Wr^T, split-K=27, atomicAdd merge
// grid = 64*27 = 1728 x 256
// ============================================================
__global__ void k4_final(const float* __restrict__ Wr,
                         float* __restrict__ out) {
    __shared__ __align__(8) float As[32][34];
    __shared__ __align__(8) float Bs[32][34];
    int bx = blockIdx.x;
    int kc   = bx % KPP;
    int tile = bx / KPP;
    int r0 = (tile >> 2) * 32;
    int j0 = (tile & 3) * 32;
    int kb = kc * 32;
    int t  = threadIdx.x;
    int lr = t >> 5;
    int kk = t & 31;
    int ty = t >> 4, tx = t & 15;
    float acc[2][2] = {};

#pragma unroll
    for (int i = 0; i < 4; i++) {
        int rr = lr + 8*i;
        As[kk][rr] = g_pool[(size_t)(r0+rr)*MTOT + kb + kk];
        Bs[kk][rr] = Wr[(size_t)(j0+rr)*MTOT + kb + kk];
    }
    __syncthreads();
#pragma unroll
    for (int q = 0; q < 32; q++) {
        float2 a  = *(const float2*)&As[q][ty*2];
        float2 bv = *(const float2*)&Bs[q][tx*2];
        acc[0][0] += a.x*bv.x; acc[0][1] += a.x*bv.y;
        acc[1][0] += a.y*bv.x; acc[1][1] += a.y*bv.y;
    }
#pragma unroll
    for (int r = 0; r < 2; r++) {
        int row = r0 + ty*2 + r;
        int b = row >> 8, p = row & 255;
#pragma unroll
        for (int c = 0; c < 2; c++) {
            int j = j0 + tx*2 + c;
            atomicAdd(&out[(size_t)b*H1*PP + (size_t)j*PP + p], acc[r][c]);
        }
    }
}

// ============================================================
extern "C" void kernel_launch(void* const* d_in, const int* in_sizes, int n_in,
                              void* d_out, int out_size) {
    const float* seed_xyz      = (const float*)d_in[0];
    const float* seed_features = (const float*)d_in[1];
    const float* boxes         = (const float*)d_in[2];
    const float* origins       = (const float*)d_in[3];
    const float* heading       = (const float*)d_in[4];
    const float* W1            = (const float*)d_in[5];
    const float* b1            = (const float*)d_in[6];
    const float* W2            = (const float*)d_in[7];
    const float* b2            = (const float*)d_in[8];
    const float* W3            = (const float*)d_in[9];
    const float* b3            = (const float*)d_in[10];
    const float* Wr            = (const float*)d_in[11];
    const float* br            = (const float*)d_in[12];
    float* out = (float*)d_out;

    k0_prep<<<1728, 256>>>(b1, br, out);
    k1_f1<<<256, 256>>>(seed_features, W1);
    k2_ballquery<<<KP_TOTAL/8, 256>>>(seed_xyz, boxes, origins, heading);
    k3_gemm<<<592, 256>>>(seed_xyz, W1, W2, b2, W3, b3);
    k4_final<<<64*KPP, 256>>>(Wr, out);
}

// round 6
// speedup vs baseline: 1.3999x; 1.3999x over previous
#include <cuda_runtime.h>

#define BB 2
#define NN 1024
#define CC 256
#define PP 256
#define KPP 27
#define NS 16
#define H1 128
#define H2 64
#define H3 32
#define MTOT (H3*KPP)          // 864
#define RADIUS 0.2f
#define KP_PER_B (PP*KPP)      // 6912
#define KP_TOTAL (BB*KP_PER_B) // 13824
#define SMAX (KP_TOTAL*NS)     // 221184

// ---- scratch ----
__device__ float g_F1[BB*NN*H1];       // feat @ W1[3:] + b1
__device__ float g_kpts[KP_TOTAL*3];
__device__ int   g_slist[SMAX];        // packed (g<<10)|n
__device__ int   g_scount;
__device__ float g_pool[BB*PP*H3*KPP]; // [b][p][c][k], atomicMax'd as int bits

// ============================================================
// K1: F1 = feat^T @ W1[3:] + b1, 64x64 tiles, double-buffered.
// Also resets g_scount (runs before k2 on same stream).
// grid = 64 x 256
// ============================================================
__global__ void k1_f1(const float* __restrict__ feat,
                      const float* __restrict__ W1,
                      const float* __restrict__ b1) {
    __shared__ __align__(16) float As[32][64];
    __shared__ __align__(16) float Bs[32][64];
    int bx = blockIdx.x;
    if (bx == 0 && threadIdx.x == 0) g_scount = 0;
    int b  = bx >> 5;
    int nt = (bx & 31) >> 1;
    int jt = bx & 1;
    int n0 = nt * 64, j0 = jt * 64;
    int t  = threadIdx.x;
    int tr = t >> 4, tc = t & 15;
    float acc[4][4] = {};
    float ra[8], rb[8];

    const float* fb = feat + (size_t)b*CC*NN;
#pragma unroll
    for (int i = 0; i < 8; i++) {
        int e = t + 256*i; int cc = e >> 6, nn = e & 63;
        ra[i] = fb[(size_t)cc*NN + n0 + nn];
        rb[i] = W1[(size_t)(3 + cc)*H1 + j0 + nn];
    }
    for (int c0 = 0; c0 < CC; c0 += 32) {
        __syncthreads();
#pragma unroll
        for (int i = 0; i < 8; i++) {
            int e = t + 256*i; int cc = e >> 6, nn = e & 63;
            As[cc][nn] = ra[i];
            Bs[cc][nn] = rb[i];
        }
        __syncthreads();
        if (c0 + 32 < CC) {
#pragma unroll
            for (int i = 0; i < 8; i++) {
                int e = t + 256*i; int cc = e >> 6, nn = e & 63;
                ra[i] = fb[(size_t)(c0+32+cc)*NN + n0 + nn];
                rb[i] = W1[(size_t)(3 + c0+32+cc)*H1 + j0 + nn];
            }
        }
#pragma unroll
        for (int kk = 0; kk < 32; kk++) {
            float4 a = *(const float4*)&As[kk][tr*4];
            float4 w = *(const float4*)&Bs[kk][tc*4];
            float av[4] = {a.x,a.y,a.z,a.w};
            float wv[4] = {w.x,w.y,w.z,w.w};
#pragma unroll
            for (int r = 0; r < 4; r++)
#pragma unroll
                for (int q = 0; q < 4; q++) acc[r][q] += av[r]*wv[q];
        }
    }
#pragma unroll
    for (int r = 0; r < 4; r++) {
        int n = n0 + tr*4 + r;
#pragma unroll
        for (int q = 0; q < 4; q++) {
            int j = j0 + tc*4 + q;
            g_F1[((size_t)b*NN + n)*H1 + j] = acc[r][q] + b1[j];
        }
    }
}

// ============================================================
// K2: keypoints + ball query + append sample list.
// Prologue also inits pool=0 and out=br (before k3/k4).
// grid = 1728 x 256
// ============================================================
__global__ void k2_ballquery(const float* __restrict__ seed_xyz,
                             const float* __restrict__ boxes,
                             const float* __restrict__ origins,
                             const float* __restrict__ heading,
                             const float* __restrict__ br,
                             float* __restrict__ out) {
    __shared__ float sx[NN], sy[NN], sz[NN], ssq[NN];
    __shared__ int sbuf[8][16];
    int t = threadIdx.x;
    {   // init pool / out (covered by 1728*256 = 442368 threads)
        int i = blockIdx.x * 256 + t;
        if (i < BB*PP*H3*KPP) ((int*)g_pool)[i] = 0;
        if (i < BB*H1*PP)     out[i] = br[(i >> 8) & 127];
    }
    int b      = blockIdx.x / (KP_PER_B / 8);
    int kpbase = (blockIdx.x % (KP_PER_B / 8)) * 8;
    for (int i = t; i < NN; i += 256) {
        float x = seed_xyz[((size_t)b*NN + i)*3 + 0];
        float y = seed_xyz[((size_t)b*NN + i)*3 + 1];
        float z = seed_xyz[((size_t)b*NN + i)*3 + 2];
        sx[i]=x; sy[i]=y; sz[i]=z; ssq[i]=x*x+y*y+z*z;
    }
    __syncthreads();

    int w = t >> 5, lane = t & 31;
    int kpid = kpbase + w;
    int g = b*KP_PER_B + kpid;
    int p = kpid / KPP, k = kpid % KPP;

    const float* bx = boxes + ((size_t)b*PP + p)*6;
    float b0=bx[0], b1v=bx[1], b2v=bx[2], b3v=bx[3], b4v=bx[4], b5v=bx[5];
    const float* og = origins + ((size_t)b*PP + p)*3;
    float h = heading[(size_t)b*PP + p];
    int i0 = k/9, i1 = (k/3)%3, i2 = k%3;
    float lx = (i0+0.5f)/3.0f*(b0+b3v) - b0;
    float ly = (i1+0.5f)/3.0f*(b1v+b4v) - b1v;
    float lz = (i2+0.5f)/3.0f*(b2v+b5v) - b2v;
    float ch = cosf(h), sh = sinf(h);
    float px =  lx*ch + ly*sh + og[0];
    float py = -lx*sh + ly*ch + og[1];
    float pz =  lz + og[2];

    float kn2 = px*px + py*py + pz*pz;
    const float r2 = RADIUS*RADIUS;
    unsigned total = 0;
    for (int base = 0; base < NN; base += 32) {
        int n = base + lane;
        float d2 = kn2 + ssq[n] - 2.0f*(px*sx[n] + py*sy[n] + pz*sz[n]);
        bool in = d2 < r2;
        unsigned m = __ballot_sync(0xffffffffu, in);
        if (m && total < 16u) {
            int before = __popc(m & ((1u << lane) - 1u));
            if (in && total + before < 16u)
                sbuf[w][total + before] = n;
        }
        total += __popc(m);
        if (total >= 16u) break;
    }
    __syncwarp();
    int stored = total < 16u ? (int)total : 16;
    int emit = stored == 0 ? 1 : stored;   // empty -> reference fill with seed 0
    int base = 0;
    if (lane == 0) base = atomicAdd(&g_scount, emit);
    base = __shfl_sync(0xffffffffu, base, 0);
    if (lane < emit) {
        int n = (stored == 0) ? 0 : sbuf[w][lane];
        g_slist[base + lane] = (g << 10) | n;
    }
    if (lane == 0) {
        g_kpts[g*3+0] = px; g_kpts[g*3+1] = py; g_kpts[g*3+2] = pz;
    }
}

// ============================================================
// K3: persistent batched MLP over compacted samples.
// W2 resident in smem (loaded ONCE). Tile = 32 samples:
// gather h1 -> GEMM(32x128x64) -> GEMM(32x64x32) -> atomicMax pool.
// grid = 296 x 256
// ============================================================
__global__ void k3_gemm(const float* __restrict__ seed_xyz,
                        const float* __restrict__ W1,
                        const float* __restrict__ W2,
                        const float* __restrict__ b2,
                        const float* __restrict__ W3,
                        const float* __restrict__ b3) {
    __shared__ __align__(16) float W2s[H1][H2];   // 32 KB, [j][o]
    __shared__ float h1T[H1][33];   // [j][s]
    __shared__ float h2T[H2][33];   // [o][s]
    __shared__ float w1s[3][H1];
    __shared__ float sm_gx[32], sm_gy[32], sm_gz[32];
    __shared__ int   sm_f1[32], sm_pb[32];
    int t = threadIdx.x;
    // one-time weight staging
#pragma unroll
    for (int q = 0; q < 8; q++) {
        int fi = t + 256*q;            // 2048 float4s
        ((float4*)W2s)[fi] = __ldg(&((const float4*)W2)[fi]);
    }
    if (t < 128) {
        w1s[0][t] = W1[t];
        w1s[1][t] = W1[128 + t];
        w1s[2][t] = W1[256 + t];
    }
    int count  = g_scount;
    int ntiles = (count + 31) >> 5;

    int s0 = t & 15, og = t >> 4, o0 = og * 4;   // GEMM1 mapping
    float4 bb = __ldg((const float4*)&b2[o0]);

    for (int tile = blockIdx.x; tile < ntiles; tile += gridDim.x) {
        __syncthreads();
        if (t < 32) {
            int pos = tile*32 + t;
            if (pos >= count) pos = count - 1;   // dup of last: idempotent under max
            int e = g_slist[pos];
            int g = e >> 10, n = e & 1023;
            int b = g / KP_PER_B;
            int rem = g % KP_PER_B;
            int p = rem / KPP, kk = rem % KPP;
            sm_pb[t] = ((b*PP + p)*H3)*KPP + kk;
            int sidx = b*NN + n;
            sm_f1[t] = sidx;
            const float* sp = seed_xyz + (size_t)sidx*3;
            sm_gx[t] = (sp[0] - g_kpts[g*3+0]) * 5.0f;
            sm_gy[t] = (sp[1] - g_kpts[g*3+1]) * 5.0f;
            sm_gz[t] = (sp[2] - g_kpts[g*3+2]) * 5.0f;
        }
        __syncthreads();
        // --- h1 gather: thread (s = t/8, u = t%8) covers j = u*16..u*16+15
        {
            int s = t >> 3, u = t & 7;
            const float* f1 = g_F1 + (size_t)sm_f1[s]*H1;
            float gx = sm_gx[s], gy = sm_gy[s], gz = sm_gz[s];
#pragma unroll
            for (int q = 0; q < 4; q++) {
                int j = u*16 + q*4;
                float4 f = __ldg((const float4*)&f1[j]);
                h1T[j+0][s] = fmaxf(f.x + gx*w1s[0][j+0] + gy*w1s[1][j+0] + gz*w1s[2][j+0], 0.f);
                h1T[j+1][s] = fmaxf(f.y + gx*w1s[0][j+1] + gy*w1s[1][j+1] + gz*w1s[2][j+1], 0.f);
                h1T[j+2][s] = fmaxf(f.z + gx*w1s[0][j+2] + gy*w1s[1][j+2] + gz*w1s[2][j+2], 0.f);
                h1T[j+3][s] = fmaxf(f.w + gx*w1s[0][j+3] + gy*w1s[1][j+3] + gz*w1s[2][j+3], 0.f);
            }
        }
        __syncthreads();
        // --- GEMM1: thread: samples {s0, s0+16}, outputs o0..o0+3
        float acc0[4] = {bb.x, bb.y, bb.z, bb.w};
        float acc1[4] = {bb.x, bb.y, bb.z, bb.w};
#pragma unroll 16
        for (int k = 0; k < H1; k++) {
            float a0 = h1T[k][s0];
            float a1 = h1T[k][s0 + 16];
            float4 wv = *(const float4*)&W2s[k][o0];
            acc0[0] = fmaf(a0, wv.x, acc0[0]); acc0[1] = fmaf(a0, wv.y, acc0[1]);
            acc0[2] = fmaf(a0, wv.z, acc0[2]); acc0[3] = fmaf(a0, wv.w, acc0[3]);
            acc1[0] = fmaf(a1, wv.x, acc1[0]); acc1[1] = fmaf(a1, wv.y, acc1[1]);
            acc1[2] = fmaf(a1, wv.z, acc1[2]); acc1[3] = fmaf(a1, wv.w, acc1[3]);
        }
#pragma unroll
        for (int q = 0; q < 4; q++) {
            h2T[o0+q][s0]      = fmaxf(acc0[q], 0.f);
            h2T[o0+q][s0 + 16] = fmaxf(acc1[q], 0.f);
        }
        __syncthreads();
        // --- GEMM2: thread: sample s = t&31, channels cg*4..+3 (W3 via L1)
        {
            int s = t & 31, cg = t >> 5;
            float4 b3v = __ldg((const float4*)&b3[cg*4]);
            float a0 = b3v.x, a1 = b3v.y, a2 = b3v.z, a3 = b3v.w;
#pragma unroll 16
            for (int k = 0; k < H2; k++) {
                float hv = h2T[k][s];
                float4 wv = __ldg((const float4*)&W3[(size_t)k*H3 + cg*4]);
                a0 = fmaf(hv, wv.x, a0); a1 = fmaf(hv, wv.y, a1);
                a2 = fmaf(hv, wv.z, a2); a3 = fmaf(hv, wv.w, a3);
            }
            int pb = sm_pb[s];
            int* pool = (int*)g_pool;
            atomicMax(&pool[pb + (cg*4+0)*KPP], __float_as_int(fmaxf(a0, 0.f)));
            atomicMax(&pool[pb + (cg*4+1)*KPP], __float_as_int(fmaxf(a1, 0.f)));
            atomicMax(&pool[pb + (cg*4+2)*KPP], __float_as_int(fmaxf(a2, 0.f)));
            atomicMax(&pool[pb + (cg*4+3)*KPP], __float_as_int(fmaxf(a3, 0.f)));
        }
    }
}

// ============================================================
// K4: out += pool @ Wr^T, split-K=27, atomicAdd merge
// grid = 64*27 = 1728 x 256
// ============================================================
__global__ void k4_final(const float* __restrict__ Wr,
                         float* __restrict__ out) {
    __shared__ __align__(8) float As[32][34];
    __shared__ __align__(8) float Bs[32][34];
    int bx = blockIdx.x;
    int kc   = bx % KPP;
    int tile = bx / KPP;
    int r0 = (tile >> 2) * 32;
    int j0 = (tile & 3) * 32;
    int kb = kc * 32;
    int t  = threadIdx.x;
    int lr = t >> 5;
    int kk = t & 31;
    int ty = t >> 4, tx = t & 15;
    float acc[2][2] = {};

#pragma unroll
    for (int i = 0; i < 4; i++) {
        int rr = lr + 8*i;
        As[kk][rr] = g_pool[(size_t)(r0+rr)*MTOT + kb + kk];
        Bs[kk][rr] = Wr[(size_t)(j0+rr)*MTOT + kb + kk];
    }
    __syncthreads();
#pragma unroll
    for (int q = 0; q < 32; q++) {
        float2 a  = *(const float2*)&As[q][ty*2];
        float2 bv = *(const float2*)&Bs[q][tx*2];
        acc[0][0] += a.x*bv.x; acc[0][1] += a.x*bv.y;
        acc[1][0] += a.y*bv.x; acc[1][1] += a.y*bv.y;
    }
#pragma unroll
    for (int r = 0; r < 2; r++) {
        int row = r0 + ty*2 + r;
        int b = row >> 8, p = row & 255;
#pragma unroll
        for (int c = 0; c < 2; c++) {
            int j = j0 + tx*2 + c;
            atomicAdd(&out[(size_t)b*H1*PP + (size_t)j*PP + p], acc[r][c]);
        }
    }
}

// ============================================================
extern "C" void kernel_launch(void* const* d_in, const int* in_sizes, int n_in,
                              void* d_out, int out_size) {
    const float* seed_xyz      = (const float*)d_in[0];
    const float* seed_features = (const float*)d_in[1];
    const float* boxes         = (const float*)d_in[2];
    const float* origins       = (const float*)d_in[3];
    const float* heading       = (const float*)d_in[4];
    const float* W1            = (const float*)d_in[5];
    const float* b1            = (const float*)d_in[6];
    const float* W2            = (const float*)d_in[7];
    const float* b2            = (const float*)d_in[8];
    const float* W3            = (const float*)d_in[9];
    const float* b3            = (const float*)d_in[10];
    const float* Wr            = (const float*)d_in[11];
    const float* br            = (const float*)d_in[12];
    float* out = (float*)d_out;

    k1_f1<<<64, 256>>>(seed_features, W1, b1);
    k2_ballquery<<<KP_TOTAL/8, 256>>>(seed_xyz, boxes, origins, heading, br, out);
    k3_gemm<<<296, 256>>>(seed_xyz, W1, W2, b2, W3, b3);
    k4_final<<<64*KPP, 256>>>(Wr, out);
}

// round 7
// speedup vs baseline: 1.5349x; 1.0964x over previous
#include <cuda_runtime.h>

#define BB 2
#define NN 1024
#define CC 256
#define PP 256
#define KPP 27
#define NS 16
#define H1 128
#define H2 64
#define H3 32
#define MTOT (H3*KPP)          // 864
#define RADIUS 0.2f
#define KP_PER_B (PP*KPP)      // 6912
#define KP_TOTAL (BB*KP_PER_B) // 13824
#define SMAX (KP_TOTAL*NS)     // 221184

#define K1_BLOCKS 64
#define K2_BLOCKS 432          // 32 keypoints per block
#define K12_BLOCKS (K1_BLOCKS + K2_BLOCKS)

// ---- scratch ----
__device__ float g_F1[BB*NN*H1];       // feat @ W1[3:] + b1
__device__ float g_kpts[KP_TOTAL*3];
__device__ int   g_slist[SMAX];        // packed (g<<10)|n
__device__ int   g_scount;             // zero at load; k4 resets each run
__device__ float g_pool[BB*PP*H3*KPP]; // [b][p][c][k], atomicMax'd as int bits

// ============================================================
// K12 (fused): blocks 0..63 -> F1 GEMM, blocks 64..495 -> ball query.
// All blocks help init pool=0 / out=br in prologue.
// ============================================================
__global__ void k12_fused(const float* __restrict__ feat,
                          const float* __restrict__ W1,
                          const float* __restrict__ b1,
                          const float* __restrict__ seed_xyz,
                          const float* __restrict__ boxes,
                          const float* __restrict__ origins,
                          const float* __restrict__ heading,
                          const float* __restrict__ br,
                          float* __restrict__ out) {
    __shared__ __align__(16) float As[32][64];
    __shared__ __align__(16) float Bs[32][64];
    __shared__ float sx[NN], sy[NN], sz[NN], ssq[NN];
    __shared__ int sbuf[8][16];
    int t = threadIdx.x;

    // prologue init (pool, out) — completes before this kernel ends,
    // consumed only by the later k3/k4 launches
    for (int i = blockIdx.x*256 + t; i < BB*PP*H3*KPP; i += K12_BLOCKS*256)
        ((int*)g_pool)[i] = 0;
    for (int i = blockIdx.x*256 + t; i < BB*H1*PP; i += K12_BLOCKS*256)
        out[i] = br[(i >> 8) & 127];

    if (blockIdx.x < K1_BLOCKS) {
        // ---------------- K1: F1 = feat^T @ W1[3:] + b1 ----------------
        int bx = blockIdx.x;
        int b  = bx >> 5;
        int nt = (bx & 31) >> 1;
        int jt = bx & 1;
        int n0 = nt * 64, j0 = jt * 64;
        int tr = t >> 4, tc = t & 15;
        float acc[4][4] = {};
        float ra[8], rb[8];

        const float* fb = feat + (size_t)b*CC*NN;
#pragma unroll
        for (int i = 0; i < 8; i++) {
            int e = t + 256*i; int cc = e >> 6, nn = e & 63;
            ra[i] = fb[(size_t)cc*NN + n0 + nn];
            rb[i] = W1[(size_t)(3 + cc)*H1 + j0 + nn];
        }
        for (int c0 = 0; c0 < CC; c0 += 32) {
            __syncthreads();
#pragma unroll
            for (int i = 0; i < 8; i++) {
                int e = t + 256*i; int cc = e >> 6, nn = e & 63;
                As[cc][nn] = ra[i];
                Bs[cc][nn] = rb[i];
            }
            __syncthreads();
            if (c0 + 32 < CC) {
#pragma unroll
                for (int i = 0; i < 8; i++) {
                    int e = t + 256*i; int cc = e >> 6, nn = e & 63;
                    ra[i] = fb[(size_t)(c0+32+cc)*NN + n0 + nn];
                    rb[i] = W1[(size_t)(3 + c0+32+cc)*H1 + j0 + nn];
                }
            }
#pragma unroll
            for (int kk = 0; kk < 32; kk++) {
                float4 a = *(const float4*)&As[kk][tr*4];
                float4 w = *(const float4*)&Bs[kk][tc*4];
                float av[4] = {a.x,a.y,a.z,a.w};
                float wv[4] = {w.x,w.y,w.z,w.w};
#pragma unroll
                for (int r = 0; r < 4; r++)
#pragma unroll
                    for (int q = 0; q < 4; q++) acc[r][q] += av[r]*wv[q];
            }
        }
#pragma unroll
        for (int r = 0; r < 4; r++) {
            int n = n0 + tr*4 + r;
#pragma unroll
            for (int q = 0; q < 4; q++) {
                int j = j0 + tc*4 + q;
                g_F1[((size_t)b*NN + n)*H1 + j] = acc[r][q] + b1[j];
            }
        }
    } else {
        // ---------------- K2: ball query, 32 keypoints / block ----------------
        int bid = blockIdx.x - K1_BLOCKS;          // 0..431
        int b      = bid / (K2_BLOCKS/BB);         // 216 blocks per batch
        int kpbase = (bid % (K2_BLOCKS/BB)) * 32;
        for (int i = t; i < NN; i += 256) {
            float x = seed_xyz[((size_t)b*NN + i)*3 + 0];
            float y = seed_xyz[((size_t)b*NN + i)*3 + 1];
            float z = seed_xyz[((size_t)b*NN + i)*3 + 2];
            sx[i]=x; sy[i]=y; sz[i]=z; ssq[i]=x*x+y*y+z*z;
        }
        __syncthreads();

        int w = t >> 5, lane = t & 31;
        const float r2 = RADIUS*RADIUS;

#pragma unroll
        for (int rr = 0; rr < 4; rr++) {
            int kpid = kpbase + rr*8 + w;
            int g = b*KP_PER_B + kpid;
            int p = kpid / KPP, k = kpid % KPP;

            const float* bx = boxes + ((size_t)b*PP + p)*6;
            float b0=bx[0], b1v=bx[1], b2v=bx[2], b3v=bx[3], b4v=bx[4], b5v=bx[5];
            const float* og = origins + ((size_t)b*PP + p)*3;
            float h = heading[(size_t)b*PP + p];
            int i0 = k/9, i1 = (k/3)%3, i2 = k%3;
            float lx = (i0+0.5f)/3.0f*(b0+b3v) - b0;
            float ly = (i1+0.5f)/3.0f*(b1v+b4v) - b1v;
            float lz = (i2+0.5f)/3.0f*(b2v+b5v) - b2v;
            float ch = cosf(h), sh = sinf(h);
            float px =  lx*ch + ly*sh + og[0];
            float py = -lx*sh + ly*ch + og[1];
            float pz =  lz + og[2];

            float kn2 = px*px + py*py + pz*pz;
            unsigned total = 0;
            for (int base = 0; base < NN; base += 32) {
                int n = base + lane;
                float d2 = kn2 + ssq[n] - 2.0f*(px*sx[n] + py*sy[n] + pz*sz[n]);
                bool in = d2 < r2;
                unsigned m = __ballot_sync(0xffffffffu, in);
                if (m && total < 16u) {
                    int before = __popc(m & ((1u << lane) - 1u));
                    if (in && total + before < 16u)
                        sbuf[w][total + before] = n;
                }
                total += __popc(m);
                if (total >= 16u) break;
            }
            __syncwarp();
            int stored = total < 16u ? (int)total : 16;
            int emit = stored == 0 ? 1 : stored;   // empty -> fill with seed 0
            int base = 0;
            if (lane == 0) base = atomicAdd(&g_scount, emit);
            base = __shfl_sync(0xffffffffu, base, 0);
            if (lane < emit) {
                int n = (stored == 0) ? 0 : sbuf[w][lane];
                g_slist[base + lane] = (g << 10) | n;
            }
            if (lane == 0) {
                g_kpts[g*3+0] = px; g_kpts[g*3+1] = py; g_kpts[g*3+2] = pz;
            }
            __syncwarp();
        }
    }
}

// ============================================================
// K3: persistent batched MLP over compacted samples.
// W2 resident in smem. Tile = 32 samples.
// grid = 296 x 256
// ============================================================
__global__ void k3_gemm(const float* __restrict__ seed_xyz,
                        const float* __restrict__ W1,
                        const float* __restrict__ W2,
                        const float* __restrict__ b2,
                        const float* __restrict__ W3,
                        const float* __restrict__ b3) {
    __shared__ __align__(16) float W2s[H1][H2];   // 32 KB, [j][o]
    __shared__ float h1T[H1][33];   // [j][s]
    __shared__ float h2T[H2][33];   // [o][s]
    __shared__ float w1s[3][H1];
    __shared__ float sm_gx[32], sm_gy[32], sm_gz[32];
    __shared__ int   sm_f1[32], sm_pb[32];
    int t = threadIdx.x;
#pragma unroll
    for (int q = 0; q < 8; q++) {
        int fi = t + 256*q;
        ((float4*)W2s)[fi] = __ldg(&((const float4*)W2)[fi]);
    }
    if (t < 128) {
        w1s[0][t] = W1[t];
        w1s[1][t] = W1[128 + t];
        w1s[2][t] = W1[256 + t];
    }
    int count  = g_scount;
    int ntiles = (count + 31) >> 5;

    int s0 = t & 15, og = t >> 4, o0 = og * 4;
    float4 bb = __ldg((const float4*)&b2[o0]);

    for (int tile = blockIdx.x; tile < ntiles; tile += gridDim.x) {
        __syncthreads();
        if (t < 32) {
            int pos = tile*32 + t;
            if (pos >= count) pos = count - 1;   // dup: idempotent under max
            int e = g_slist[pos];
            int g = e >> 10, n = e & 1023;
            int b = g / KP_PER_B;
            int rem = g % KP_PER_B;
            int p = rem / KPP, kk = rem % KPP;
            sm_pb[t] = ((b*PP + p)*H3)*KPP + kk;
            int sidx = b*NN + n;
            sm_f1[t] = sidx;
            const float* sp = seed_xyz + (size_t)sidx*3;
            sm_gx[t] = (sp[0] - g_kpts[g*3+0]) * 5.0f;
            sm_gy[t] = (sp[1] - g_kpts[g*3+1]) * 5.0f;
            sm_gz[t] = (sp[2] - g_kpts[g*3+2]) * 5.0f;
        }
        __syncthreads();
        {
            int s = t >> 3, u = t & 7;
            const float* f1 = g_F1 + (size_t)sm_f1[s]*H1;
            float gx = sm_gx[s], gy = sm_gy[s], gz = sm_gz[s];
#pragma unroll
            for (int q = 0; q < 4; q++) {
                int j = u*16 + q*4;
                float4 f = __ldg((const float4*)&f1[j]);
                h1T[j+0][s] = fmaxf(f.x + gx*w1s[0][j+0] + gy*w1s[1][j+0] + gz*w1s[2][j+0], 0.f);
                h1T[j+1][s] = fmaxf(f.y + gx*w1s[0][j+1] + gy*w1s[1][j+1] + gz*w1s[2][j+1], 0.f);
                h1T[j+2][s] = fmaxf(f.z + gx*w1s[0][j+2] + gy*w1s[1][j+2] + gz*w1s[2][j+2], 0.f);
                h1T[j+3][s] = fmaxf(f.w + gx*w1s[0][j+3] + gy*w1s[1][j+3] + gz*w1s[2][j+3], 0.f);
            }
        }
        __syncthreads();
        float acc0[4] = {bb.x, bb.y, bb.z, bb.w};
        float acc1[4] = {bb.x, bb.y, bb.z, bb.w};
#pragma unroll 16
        for (int k = 0; k < H1; k++) {
            float a0 = h1T[k][s0];
            float a1 = h1T[k][s0 + 16];
            float4 wv = *(const float4*)&W2s[k][o0];
            acc0[0] = fmaf(a0, wv.x, acc0[0]); acc0[1] = fmaf(a0, wv.y, acc0[1]);
            acc0[2] = fmaf(a0, wv.z, acc0[2]); acc0[3] = fmaf(a0, wv.w, acc0[3]);
            acc1[0] = fmaf(a1, wv.x, acc1[0]); acc1[1] = fmaf(a1, wv.y, acc1[1]);
            acc1[2] = fmaf(a1, wv.z, acc1[2]); acc1[3] = fmaf(a1, wv.w, acc1[3]);
        }
#pragma unroll
        for (int q = 0; q < 4; q++) {
            h2T[o0+q][s0]      = fmaxf(acc0[q], 0.f);
            h2T[o0+q][s0 + 16] = fmaxf(acc1[q], 0.f);
        }
        __syncthreads();
        {
            int s = t & 31, cg = t >> 5;
            float4 b3v = __ldg((const float4*)&b3[cg*4]);
            float a0 = b3v.x, a1 = b3v.y, a2 = b3v.z, a3 = b3v.w;
#pragma unroll 16
            for (int k = 0; k < H2; k++) {
                float hv = h2T[k][s];
                float4 wv = __ldg((const float4*)&W3[(size_t)k*H3 + cg*4]);
                a0 = fmaf(hv, wv.x, a0); a1 = fmaf(hv, wv.y, a1);
                a2 = fmaf(hv, wv.z, a2); a3 = fmaf(hv, wv.w, a3);
            }
            int pb = sm_pb[s];
            int* pool = (int*)g_pool;
            atomicMax(&pool[pb + (cg*4+0)*KPP], __float_as_int(fmaxf(a0, 0.f)));
            atomicMax(&pool[pb + (cg*4+1)*KPP], __float_as_int(fmaxf(a1, 0.f)));
            atomicMax(&pool[pb + (cg*4+2)*KPP], __float_as_int(fmaxf(a2, 0.f)));
            atomicMax(&pool[pb + (cg*4+3)*KPP], __float_as_int(fmaxf(a3, 0.f)));
        }
    }
}

// ============================================================
// K4: out += pool @ Wr^T. 64x64 tiles, split-K=9 (96 k / block),
// register prefetch. grid = 16 tiles * 9 = 144 x 256.
// Also resets g_scount for next run.
// ============================================================
__global__ void k4_final(const float* __restrict__ Wr,
                         float* __restrict__ out) {
    __shared__ __align__(16) float As[32][68];  // [kk][row], padded
    __shared__ __align__(16) float Bs[32][68];  // [kk][j]
    int t = threadIdx.x;
    if (blockIdx.x == 0 && t == 0) g_scount = 0;
    int tile = blockIdx.x & 15;
    int kc   = blockIdx.x >> 4;           // 0..8
    int r0 = (tile >> 1) * 64;
    int j0 = (tile & 1) * 64;
    int kb = kc * 96;
    int tr = t >> 4, tc = t & 15;         // tr -> j group, tc -> row group
    float acc[4][4] = {};
    float ra[8], rb[8];

#pragma unroll
    for (int i = 0; i < 8; i++) {
        int e = t + 256*i; int kk = e & 31, rr = e >> 5;
        ra[i] = g_pool[(size_t)(r0+rr)*MTOT + kb + kk];
        rb[i] = Wr[(size_t)(j0+rr)*MTOT + kb + kk];
    }
#pragma unroll
    for (int c = 0; c < 3; c++) {
        __syncthreads();
#pragma unroll
        for (int i = 0; i < 8; i++) {
            int e = t + 256*i; int kk = e & 31, rr = e >> 5;
            As[kk][rr] = ra[i];
            Bs[kk][rr] = rb[i];
        }
        __syncthreads();
        if (c < 2) {
#pragma unroll
            for (int i = 0; i < 8; i++) {
                int e = t + 256*i; int kk = e & 31, rr = e >> 5;
                ra[i] = g_pool[(size_t)(r0+rr)*MTOT + kb + (c+1)*32 + kk];
                rb[i] = Wr[(size_t)(j0+rr)*MTOT + kb + (c+1)*32 + kk];
            }
        }
#pragma unroll
        for (int kk = 0; kk < 32; kk++) {
            float4 a = *(const float4*)&As[kk][tc*4];
            float4 w = *(const float4*)&Bs[kk][tr*4];
            float av[4] = {a.x,a.y,a.z,a.w};
            float wv[4] = {w.x,w.y,w.z,w.w};
#pragma unroll
            for (int r = 0; r < 4; r++)
#pragma unroll
                for (int q = 0; q < 4; q++) acc[r][q] += av[r]*wv[q];
        }
    }
#pragma unroll
    for (int r = 0; r < 4; r++) {
        int row = r0 + tc*4 + r;
        int b = row >> 8, p = row & 255;
#pragma unroll
        for (int q = 0; q < 4; q++) {
            int j = j0 + tr*4 + q;
            atomicAdd(&out[(size_t)b*H1*PP + (size_t)j*PP + p], acc[r][q]);
        }
    }
}

// ============================================================
extern "C" void kernel_launch(void* const* d_in, const int* in_sizes, int n_in,
                              void* d_out, int out_size) {
    const float* seed_xyz      = (const float*)d_in[0];
    const float* seed_features = (const float*)d_in[1];
    const float* boxes         = (const float*)d_in[2];
    const float* origins       = (const float*)d_in[3];
    const float* heading       = (const float*)d_in[4];
    const float* W1            = (const float*)d_in[5];
    const float* b1            = (const float*)d_in[6];
    const float* W2            = (const float*)d_in[7];
    const float* b2            = (const float*)d_in[8];
    const float* W3            = (const float*)d_in[9];
    const float* b3            = (const float*)d_in[10];
    const float* Wr            = (const float*)d_in[11];
    const float* br            = (const float*)d_in[12];
    float* out = (float*)d_out;

    k12_fused<<<K12_BLOCKS, 256>>>(seed_features, W1, b1,
                                   seed_xyz, boxes, origins, heading, br, out);
    k3_gemm<<<296, 256>>>(seed_xyz, W1, W2, b2, W3, b3);
    k4_final<<<144, 256>>>(Wr, out);
}

// round 10
// speedup vs baseline: 1.5356x; 1.0005x over previous
#include <cuda_runtime.h>

#define BB 2
#define NN 1024
#define CC 256
#define PP 256
#define KPP 27
#define NS 16
#define H1 128
#define H2 64
#define H3 32
#define MTOT (H3*KPP)          // 864
#define RADIUS 0.2f
#define KP_PER_B (PP*KPP)      // 6912
#define KP_TOTAL (BB*KP_PER_B) // 13824
#define SMAX (KP_TOTAL*NS)     // 221184

#define K1_BLOCKS 128
#define K2_BLOCKS 216          // 64 keypoints per block (2 groups x 32)
#define K12_BLOCKS (K1_BLOCKS + K2_BLOCKS)

// ---- scratch ----
__device__ float g_F1[BB*NN*H1];       // feat @ W1[3:] + b1
__device__ float g_kpts[KP_TOTAL*3];
__device__ int   g_slist[SMAX];        // packed (g<<10)|n
__device__ int   g_scount;             // zero at load; k4 resets each run
__device__ float g_pool[BB*PP*H3*KPP]; // [b][p][c][k], atomicMax'd as int bits

// ============================================================
// K12 (fused): blocks 0..127 -> F1 GEMM (64x32 tiles),
//              blocks 128..343 -> ball query (lane-per-keypoint).
// All blocks help init pool=0 / out=br in prologue.
// ============================================================
__global__ void k12_fused(const float* __restrict__ feat,
                          const float* __restrict__ W1,
                          const float* __restrict__ b1,
                          const float* __restrict__ seed_xyz,
                          const float* __restrict__ boxes,
                          const float* __restrict__ origins,
                          const float* __restrict__ heading,
                          const float* __restrict__ br,
                          float* __restrict__ out) {
    // GEMM half
    __shared__ __align__(16) float As[32][64];   // 8 KB
    __shared__ __align__(16) float Bs[32][32];   // 4 KB
    // ball half
    __shared__ __align__(16) float4 s4[NN];      // 16 KB  {x,y,z,|s|^2}
    __shared__ int sbuf2[2][4][32][16];          // 16 KB
    __shared__ int scnt[2][4][32];               // 1 KB
    int t = threadIdx.x;

    for (int i = blockIdx.x*256 + t; i < BB*PP*H3*KPP; i += K12_BLOCKS*256)
        ((int*)g_pool)[i] = 0;
    for (int i = blockIdx.x*256 + t; i < BB*H1*PP; i += K12_BLOCKS*256)
        out[i] = br[(i >> 8) & 127];

    if (blockIdx.x < K1_BLOCKS) {
        // ---------------- K1: F1 = feat^T @ W1[3:] + b1 ----------------
        int bx = blockIdx.x;
        int b  = bx >> 6;
        int r_ = bx & 63;
        int nt = r_ >> 2, jt = r_ & 3;
        int n0 = nt * 64, j0 = jt * 32;
        int tn = t & 15, tj = t >> 4;
        float acc[4][2] = {};
        float ra[8], rb[4];

        const float* fb = feat + (size_t)b*CC*NN;
#pragma unroll
        for (int i = 0; i < 8; i++) {
            int e = t + 256*i; int cc = e >> 6, nn = e & 63;
            ra[i] = fb[(size_t)cc*NN + n0 + nn];
        }
#pragma unroll
        for (int i = 0; i < 4; i++) {
            int e = t + 256*i; int cc = e >> 5, jj = e & 31;
            rb[i] = W1[(size_t)(3 + cc)*H1 + j0 + jj];
        }
        for (int c0 = 0; c0 < CC; c0 += 32) {
            __syncthreads();
#pragma unroll
            for (int i = 0; i < 8; i++) {
                int e = t + 256*i; As[e >> 6][e & 63] = ra[i];
            }
#pragma unroll
            for (int i = 0; i < 4; i++) {
                int e = t + 256*i; Bs[e >> 5][e & 31] = rb[i];
            }
            __syncthreads();
            if (c0 + 32 < CC) {
#pragma unroll
                for (int i = 0; i < 8; i++) {
                    int e = t + 256*i; int cc = e >> 6, nn = e & 63;
                    ra[i] = fb[(size_t)(c0+32+cc)*NN + n0 + nn];
                }
#pragma unroll
                for (int i = 0; i < 4; i++) {
                    int e = t + 256*i; int cc = e >> 5, jj = e & 31;
                    rb[i] = W1[(size_t)(3 + c0+32+cc)*H1 + j0 + jj];
                }
            }
#pragma unroll
            for (int kk = 0; kk < 32; kk++) {
                float4 a = *(const float4*)&As[kk][tn*4];
                float2 w = *(const float2*)&Bs[kk][tj*2];
                float av[4] = {a.x,a.y,a.z,a.w};
#pragma unroll
                for (int r = 0; r < 4; r++) {
                    acc[r][0] += av[r]*w.x;
                    acc[r][1] += av[r]*w.y;
                }
            }
        }
        int j = j0 + tj*2;
        float bb0 = b1[j], bb1 = b1[j+1];
#pragma unroll
        for (int r = 0; r < 4; r++) {
            int n = n0 + tn*4 + r;
            float2 v = make_float2(acc[r][0] + bb0, acc[r][1] + bb1);
            *(float2*)&g_F1[((size_t)b*NN + n)*H1 + j] = v;
        }
    } else {
        // ---------------- K2: ball query, lane = keypoint ----------------
        int bid = blockIdx.x - K1_BLOCKS;        // 0..215
        int b   = bid / (K2_BLOCKS/BB);          // 108 blocks per batch
        int kp0 = (bid % (K2_BLOCKS/BB)) * 64;
        // stage seeds as float4
        for (int i = t; i < NN; i += 256) {
            const float* sp = seed_xyz + ((size_t)b*NN + i)*3;
            float x = sp[0], y = sp[1], z = sp[2];
            s4[i] = make_float4(x, y, z, x*x + y*y + z*z);
        }
        __syncthreads();

        int w = t >> 5, lane = t & 31;
        int grp = w >> 2, ch = w & 3;
        int kpid = kp0 + grp*32 + lane;
        int g = b*KP_PER_B + kpid;
        int p = kpid / KPP, k = kpid % KPP;

        const float* bx = boxes + ((size_t)b*PP + p)*6;
        float b0=bx[0], b1v=bx[1], b2v=bx[2], b3v=bx[3], b4v=bx[4], b5v=bx[5];
        const float* og = origins + ((size_t)b*PP + p)*3;
        float h = heading[(size_t)b*PP + p];
        int i0 = k/9, i1 = (k/3)%3, i2 = k%3;
        float lx = (i0+0.5f)/3.0f*(b0+b3v) - b0;
        float ly = (i1+0.5f)/3.0f*(b1v+b4v) - b1v;
        float lz = (i2+0.5f)/3.0f*(b2v+b5v) - b2v;
        float chh = cosf(h), shh = sinf(h);
        float px =  lx*chh + ly*shh + og[0];
        float py = -lx*shh + ly*chh + og[1];
        float pz =  lz + og[2];

        float px2 = -2.0f*px, py2 = -2.0f*py, pz2 = -2.0f*pz;
        float base = px*px + py*py + pz*pz - RADIUS*RADIUS;

        int cnt = 0;
        int* myslot = &sbuf2[grp][ch][lane][0];
        int nb = ch * 256;
#pragma unroll 4
        for (int i = 0; i < 256; i++) {
            float4 sv = s4[nb + i];
            float v = base + sv.w + px2*sv.x + py2*sv.y + pz2*sv.z;
            if (v < 0.0f && cnt < 16) { myslot[cnt] = nb + i; cnt++; }
        }
        scnt[grp][ch][lane] = cnt;
        if (ch == 0) {
            g_kpts[g*3+0] = px; g_kpts[g*3+1] = py; g_kpts[g*3+2] = pz;
        }
        __syncthreads();
        // merge (chunk order == index order): warps with ch==0
        if (ch == 0) {
            int c0 = scnt[grp][0][lane], c1 = scnt[grp][1][lane];
            int c2 = scnt[grp][2][lane], c3 = scnt[grp][3][lane];
            int tot = c0 + c1 + c2 + c3;
            int take = tot < 16 ? tot : 16;
            int emit = take == 0 ? 1 : take;
            // inclusive warp scan of emit
            int off = emit;
#pragma unroll
            for (int d = 1; d < 32; d <<= 1) {
                int v = __shfl_up_sync(0xffffffffu, off, d);
                if (lane >= d) off += v;
            }
            int total_emit = __shfl_sync(0xffffffffu, off, 31);
            int base_g = 0;
            if (lane == 31) base_g = atomicAdd(&g_scount, total_emit);
            base_g = __shfl_sync(0xffffffffu, base_g, 31);
            int mybase = base_g + off - emit;
            if (take == 0) {
                g_slist[mybase] = (g << 10);   // reference fill -> seed 0
            } else {
                int written = 0;
#pragma unroll
                for (int c = 0; c < 4; c++) {
                    int cc = scnt[grp][c][lane];
                    for (int i2v = 0; i2v < cc && written < take; i2v++) {
                        g_slist[mybase + written] = (g << 10) | sbuf2[grp][c][lane][i2v];
                        written++;
                    }
                }
            }
        }
    }
}

// ============================================================
// K3: persistent batched MLP. Tile = 64 samples.
// W2/W3 via warp-uniform __ldg broadcast; h1/h2 in smem.
// grid = 296 x 256
// ============================================================
__global__ void k3_gemm(const float* __restrict__ seed_xyz,
                        const float* __restrict__ W1,
                        const float* __restrict__ W2,
                        const float* __restrict__ b2,
                        const float* __restrict__ W3,
                        const float* __restrict__ b3) {
    __shared__ float h1T[H1][65];   // [j][s] 33.3 KB
    __shared__ float h2T[H2][65];   // [o][s] 16.6 KB
    __shared__ float w1s[3][H1];
    __shared__ float sgx[64], sgy[64], sgz[64];
    __shared__ int   sf1[64], spb[64];
    int t = threadIdx.x;
    if (t < 128) {
        w1s[0][t] = W1[t];
        w1s[1][t] = W1[128 + t];
        w1s[2][t] = W1[256 + t];
    }
    int count  = g_scount;
    int ntiles = (count + 63) >> 6;

    int s0 = t & 31;
    int o0 = (t >> 5) * 8;          // GEMM1: 8 outputs
    int cg4 = (t >> 5) * 4;         // GEMM2: 4 channels
    float4 bb0 = __ldg((const float4*)&b2[o0]);
    float4 bb1 = __ldg((const float4*)&b2[o0+4]);
    float4 b3v = __ldg((const float4*)&b3[cg4]);

    for (int tile = blockIdx.x; tile < ntiles; tile += gridDim.x) {
        __syncthreads();
        if (t < 64) {
            int pos = tile*64 + t;
            if (pos >= count) pos = count - 1;   // dup: idempotent under max
            int e = g_slist[pos];
            int g = e >> 10, n = e & 1023;
            int b = g / KP_PER_B;
            int rem = g % KP_PER_B;
            int p = rem / KPP, kk = rem % KPP;
            spb[t] = ((b*PP + p)*H3)*KPP + kk;
            int sidx = b*NN + n;
            sf1[t] = sidx;
            const float* sp = seed_xyz + (size_t)sidx*3;
            sgx[t] = (sp[0] - g_kpts[g*3+0]) * 5.0f;
            sgy[t] = (sp[1] - g_kpts[g*3+1]) * 5.0f;
            sgz[t] = (sp[2] - g_kpts[g*3+2]) * 5.0f;
        }
        __syncthreads();
        // --- h1 gather: s = t&63, u = t>>6 covers j = u*32 .. +31
        {
            int s = t & 63, u = t >> 6;
            const float* f1 = g_F1 + (size_t)sf1[s]*H1;
            float gx = sgx[s], gy = sgy[s], gz = sgz[s];
#pragma unroll
            for (int q = 0; q < 8; q++) {
                int j = u*32 + q*4;
                float4 f = __ldg((const float4*)&f1[j]);
                h1T[j+0][s] = fmaxf(f.x + gx*w1s[0][j+0] + gy*w1s[1][j+0] + gz*w1s[2][j+0], 0.f);
                h1T[j+1][s] = fmaxf(f.y + gx*w1s[0][j+1] + gy*w1s[1][j+1] + gz*w1s[2][j+1], 0.f);
                h1T[j+2][s] = fmaxf(f.z + gx*w1s[0][j+2] + gy*w1s[1][j+2] + gz*w1s[2][j+2], 0.f);
                h1T[j+3][s] = fmaxf(f.w + gx*w1s[0][j+3] + gy*w1s[1][j+3] + gz*w1s[2][j+3], 0.f);
            }
        }
        __syncthreads();
        // --- GEMM1: 2 samples (s0, s0+32) x 8 outputs (o0..o0+7)
        float a0[8] = {bb0.x,bb0.y,bb0.z,bb0.w, bb1.x,bb1.y,bb1.z,bb1.w};
        float a1[8] = {bb0.x,bb0.y,bb0.z,bb0.w, bb1.x,bb1.y,bb1.z,bb1.w};
#pragma unroll 8
        for (int k = 0; k < H1; k++) {
            float ha = h1T[k][s0];
            float hb = h1T[k][s0 + 32];
            float4 w0 = __ldg((const float4*)&W2[(size_t)k*H2 + o0]);
            float4 w1 = __ldg((const float4*)&W2[(size_t)k*H2 + o0 + 4]);
            a0[0] = fmaf(ha, w0.x, a0[0]); a0[1] = fmaf(ha, w0.y, a0[1]);
            a0[2] = fmaf(ha, w0.z, a0[2]); a0[3] = fmaf(ha, w0.w, a0[3]);
            a0[4] = fmaf(ha, w1.x, a0[4]); a0[5] = fmaf(ha, w1.y, a0[5]);
            a0[6] = fmaf(ha, w1.z, a0[6]); a0[7] = fmaf(ha, w1.w, a0[7]);
            a1[0] = fmaf(hb, w0.x, a1[0]); a1[1] = fmaf(hb, w0.y, a1[1]);
            a1[2] = fmaf(hb, w0.z, a1[2]); a1[3] = fmaf(hb, w0.w, a1[3]);
            a1[4] = fmaf(hb, w1.x, a1[4]); a1[5] = fmaf(hb, w1.y, a1[5]);
            a1[6] = fmaf(hb, w1.z, a1[6]); a1[7] = fmaf(hb, w1.w, a1[7]);
        }
#pragma unroll
        for (int q = 0; q < 8; q++) {
            h2T[o0+q][s0]      = fmaxf(a0[q], 0.f);
            h2T[o0+q][s0 + 32] = fmaxf(a1[q], 0.f);
        }
        __syncthreads();
        // --- GEMM2: 2 samples x 4 channels (cg4..+3)
        {
            float c0[4] = {b3v.x, b3v.y, b3v.z, b3v.w};
            float c1[4] = {b3v.x, b3v.y, b3v.z, b3v.w};
#pragma unroll 8
            for (int k = 0; k < H2; k++) {
                float ha = h2T[k][s0];
                float hb = h2T[k][s0 + 32];
                float4 wv = __ldg((const float4*)&W3[(size_t)k*H3 + cg4]);
                c0[0] = fmaf(ha, wv.x, c0[0]); c0[1] = fmaf(ha, wv.y, c0[1]);
                c0[2] = fmaf(ha, wv.z, c0[2]); c0[3] = fmaf(ha, wv.w, c0[3]);
                c1[0] = fmaf(hb, wv.x, c1[0]); c1[1] = fmaf(hb, wv.y, c1[1]);
                c1[2] = fmaf(hb, wv.z, c1[2]); c1[3] = fmaf(hb, wv.w, c1[3]);
            }
            int pba = spb[s0], pbb = spb[s0 + 32];
            int* pool = (int*)g_pool;
#pragma unroll
            for (int q = 0; q < 4; q++) {
                atomicMax(&pool[pba + (cg4+q)*KPP], __float_as_int(fmaxf(c0[q], 0.f)));
                atomicMax(&pool[pbb + (cg4+q)*KPP], __float_as_int(fmaxf(c1[q], 0.f)));
            }
        }
    }
}

// ============================================================
// K4: out += pool @ Wr^T. 64x64 tiles, split-K=9 (96 k / block),
// register prefetch. grid = 144 x 256. Resets g_scount.
// ============================================================
__global__ void k4_final(const float* __restrict__ Wr,
                         float* __restrict__ out) {
    __shared__ __align__(16) float As[32][68];
    __shared__ __align__(16) float Bs[32][68];
    int t = threadIdx.x;
    if (blockIdx.x == 0 && t == 0) g_scount = 0;
    int tile = blockIdx.x & 15;
    int kc   = blockIdx.x >> 4;
    int r0 = (tile >> 1) * 64;
    int j0 = (tile & 1) * 64;
    int kb = kc * 96;
    int tr = t >> 4, tc = t & 15;
    float acc[4][4] = {};
    float ra[8], rb[8];

#pragma unroll
    for (int i = 0; i < 8; i++) {
        int e = t + 256*i; int kk = e & 31, rr = e >> 5;
        ra[i] = g_pool[(size_t)(r0+rr)*MTOT + kb + kk];
        rb[i] = Wr[(size_t)(j0+rr)*MTOT + kb + kk];
    }
#pragma unroll
    for (int c = 0; c < 3; c++) {
        __syncthreads();
#pragma unroll
        for (int i = 0; i < 8; i++) {
            int e = t + 256*i; int kk = e & 31, rr = e >> 5;
            As[kk][rr] = ra[i];
            Bs[kk][rr] = rb[i];
        }
        __syncthreads();
        if (c < 2) {
#pragma unroll
            for (int i = 0; i < 8; i++) {
                int e = t + 256*i; int kk = e & 31, rr = e >> 5;
                ra[i] = g_pool[(size_t)(r0+rr)*MTOT + kb + (c+1)*32 + kk];
                rb[i] = Wr[(size_t)(j0+rr)*MTOT + kb + (c+1)*32 + kk];
            }
        }
#pragma unroll
        for (int kk = 0; kk < 32; kk++) {
            float4 a = *(const float4*)&As[kk][tc*4];
            float4 w = *(const float4*)&Bs[kk][tr*4];
            float av[4] = {a.x,a.y,a.z,a.w};
            float wv[4] = {w.x,w.y,w.z,w.w};
#pragma unroll
            for (int r = 0; r < 4; r++)
#pragma unroll
                for (int q = 0; q < 4; q++) acc[r][q] += av[r]*wv[q];
        }
    }
#pragma unroll
    for (int r = 0; r < 4; r++) {
        int row = r0 + tc*4 + r;
        int b = row >> 8, p = row & 255;
#pragma unroll
        for (int q = 0; q < 4; q++) {
            int j = j0 + tr*4 + q;
            atomicAdd(&out[(size_t)b*H1*PP + (size_t)j*PP + p], acc[r][q]);
        }
    }
}

// ============================================================
extern "C" void kernel_launch(void* const* d_in, const int* in_sizes, int n_in,
                              void* d_out, int out_size) {
    const float* seed_xyz      = (const float*)d_in[0];
    const float* seed_features = (const float*)d_in[1];
    const float* boxes         = (const float*)d_in[2];
    const float* origins       = (const float*)d_in[3];
    const float* heading       = (const float*)d_in[4];
    const float* W1            = (const float*)d_in[5];
    const float* b1            = (const float*)d_in[6];
    const float* W2            = (const float*)d_in[7];
    const float* b2            = (const float*)d_in[8];
    const float* W3            = (const float*)d_in[9];
    const float* b3            = (const float*)d_in[10];
    const float* Wr            = (const float*)d_in[11];
    const float* br            = (const float*)d_in[12];
    float* out = (float*)d_out;

    k12_fused<<<K12_BLOCKS, 256>>>(seed_features, W1, b1,
                                   seed_xyz, boxes, origins, heading, br, out);
    k3_gemm<<<296, 256>>>(seed_xyz, W1, W2, b2, W3, b3);
    k4_final<<<144, 256>>>(Wr, out);
}

// round 15
// speedup vs baseline: 1.8093x; 1.1782x over previous
#include <cuda_runtime.h>

#define BB 2
#define NN 1024
#define CC 256
#define PP 256
#define KPP 27
#define NS 16
#define H1 128
#define H2 64
#define H3 32
#define MTOT (H3*KPP)          // 864
#define RADIUS 0.2f
#define KP_PER_B (PP*KPP)      // 6912
#define KP_TOTAL (BB*KP_PER_B) // 13824
#define SMAX (KP_TOTAL*NS)     // 221184

#define K1_BLOCKS 128
#define K2_BLOCKS 432          // 32 keypoints per block, 8 chunk-warps x 128 seeds
#define K12_BLOCKS (K1_BLOCKS + K2_BLOCKS)

// ---- scratch ----
__device__ float g_F1[BB*NN*H1];       // feat @ W1[3:] + b1
__device__ float g_kpts[KP_TOTAL*3];
__device__ int   g_slist[SMAX];        // packed (g<<10)|n
__device__ int   g_scount;             // zero at load; k4 resets each run
__device__ float g_pool[BB*PP*H3*KPP]; // [b][p][c][k], atomicMax'd as int bits

// ============================================================
// K12 (fused): blocks 0..127 -> F1 GEMM (64x32 tiles),
//              blocks 128..559 -> ball query (lane = keypoint,
//              warp = 128-seed chunk). smem UNIONed: 25 KB.
// ============================================================
__global__ void k12_fused(const float* __restrict__ feat,
                          const float* __restrict__ W1,
                          const float* __restrict__ b1,
                          const float* __restrict__ seed_xyz,
                          const float* __restrict__ boxes,
                          const float* __restrict__ origins,
                          const float* __restrict__ heading,
                          const float* __restrict__ br,
                          float* __restrict__ out) {
    __shared__ union {
        struct {
            float As[32][64];                 // 8 KB
            float Bs[32][32];                 // 4 KB
        } g;
        struct {
            float4 s4[NN];                    // 16 KB {x,y,z,|s|^2}
            unsigned short sbuf[8][32][16];   // 8 KB  [chunk][kp][slot]
            int scnt[8][32];                  // 1 KB
        } q;
    } sm;
    int t = threadIdx.x;

    for (int i = blockIdx.x*256 + t; i < BB*PP*H3*KPP; i += K12_BLOCKS*256)
        ((int*)g_pool)[i] = 0;
    for (int i = blockIdx.x*256 + t; i < BB*H1*PP; i += K12_BLOCKS*256)
        out[i] = br[(i >> 8) & 127];

    if (blockIdx.x < K1_BLOCKS) {
        // ---------------- K1: F1 = feat^T @ W1[3:] + b1 ----------------
        int bx = blockIdx.x;
        int b  = bx >> 6;
        int r_ = bx & 63;
        int nt = r_ >> 2, jt = r_ & 3;
        int n0 = nt * 64, j0 = jt * 32;
        int tn = t & 15, tj = t >> 4;
        float acc[4][2] = {};
        float ra[8], rb[4];

        const float* fb = feat + (size_t)b*CC*NN;
#pragma unroll
        for (int i = 0; i < 8; i++) {
            int e = t + 256*i; int cc = e >> 6, nn = e & 63;
            ra[i] = fb[(size_t)cc*NN + n0 + nn];
        }
#pragma unroll
        for (int i = 0; i < 4; i++) {
            int e = t + 256*i; int cc = e >> 5, jj = e & 31;
            rb[i] = W1[(size_t)(3 + cc)*H1 + j0 + jj];
        }
        for (int c0 = 0; c0 < CC; c0 += 32) {
            __syncthreads();
#pragma unroll
            for (int i = 0; i < 8; i++) {
                int e = t + 256*i; sm.g.As[e >> 6][e & 63] = ra[i];
            }
#pragma unroll
            for (int i = 0; i < 4; i++) {
                int e = t + 256*i; sm.g.Bs[e >> 5][e & 31] = rb[i];
            }
            __syncthreads();
            if (c0 + 32 < CC) {
#pragma unroll
                for (int i = 0; i < 8; i++) {
                    int e = t + 256*i; int cc = e >> 6, nn = e & 63;
                    ra[i] = fb[(size_t)(c0+32+cc)*NN + n0 + nn];
                }
#pragma unroll
                for (int i = 0; i < 4; i++) {
                    int e = t + 256*i; int cc = e >> 5, jj = e & 31;
                    rb[i] = W1[(size_t)(3 + c0+32+cc)*H1 + j0 + jj];
                }
            }
#pragma unroll
            for (int kk = 0; kk < 32; kk++) {
                float4 a = *(const float4*)&sm.g.As[kk][tn*4];
                float2 w = *(const float2*)&sm.g.Bs[kk][tj*2];
                float av[4] = {a.x,a.y,a.z,a.w};
#pragma unroll
                for (int r = 0; r < 4; r++) {
                    acc[r][0] += av[r]*w.x;
                    acc[r][1] += av[r]*w.y;
                }
            }
        }
        int j = j0 + tj*2;
        float bb0 = b1[j], bb1 = b1[j+1];
#pragma unroll
        for (int r = 0; r < 4; r++) {
            int n = n0 + tn*4 + r;
            float2 v = make_float2(acc[r][0] + bb0, acc[r][1] + bb1);
            *(float2*)&g_F1[((size_t)b*NN + n)*H1 + j] = v;
        }
    } else {
        // ---------------- K2: ball query ----------------
        int bid = blockIdx.x - K1_BLOCKS;        // 0..431
        int b   = bid / (K2_BLOCKS/BB);          // 216 blocks per batch
        int kp0 = (bid % (K2_BLOCKS/BB)) * 32;
        for (int i = t; i < NN; i += 256) {
            const float* sp = seed_xyz + ((size_t)b*NN + i)*3;
            float x = sp[0], y = sp[1], z = sp[2];
            sm.q.s4[i] = make_float4(x, y, z, x*x + y*y + z*z);
        }
        __syncthreads();

        int w = t >> 5, lane = t & 31;   // w = chunk, lane = keypoint
        int kpid = kp0 + lane;
        int g = b*KP_PER_B + kpid;
        int p = kpid / KPP, k = kpid % KPP;

        const float* bx = boxes + ((size_t)b*PP + p)*6;
        float b0=bx[0], b1v=bx[1], b2v=bx[2], b3v=bx[3], b4v=bx[4], b5v=bx[5];
        const float* og = origins + ((size_t)b*PP + p)*3;
        float h = heading[(size_t)b*PP + p];
        int i0 = k/9, i1 = (k/3)%3, i2 = k%3;
        float lx = (i0+0.5f)/3.0f*(b0+b3v) - b0;
        float ly = (i1+0.5f)/3.0f*(b1v+b4v) - b1v;
        float lz = (i2+0.5f)/3.0f*(b2v+b5v) - b2v;
        float chh = cosf(h), shh = sinf(h);
        float px =  lx*chh + ly*shh + og[0];
        float py = -lx*shh + ly*chh + og[1];
        float pz =  lz + og[2];

        float px2 = -2.0f*px, py2 = -2.0f*py, pz2 = -2.0f*pz;
        float base = px*px + py*py + pz*pz - RADIUS*RADIUS;

        int cnt = 0;
        unsigned short* myslot = &sm.q.sbuf[w][lane][0];
        int nb = w * 128;
#pragma unroll 4
        for (int i = 0; i < 128; i++) {
            float4 sv = sm.q.s4[nb + i];
            float v = base + sv.w + px2*sv.x + py2*sv.y + pz2*sv.z;
            if (v < 0.0f && cnt < 16) { myslot[cnt] = (unsigned short)(nb + i); cnt++; }
        }
        sm.q.scnt[w][lane] = cnt;
        if (w == 0) {
            g_kpts[g*3+0] = px; g_kpts[g*3+1] = py; g_kpts[g*3+2] = pz;
        }
        __syncthreads();
        // merge in chunk order (== ascending seed index) by warp 0
        if (w == 0) {
            int tot = 0;
#pragma unroll
            for (int c = 0; c < 8; c++) tot += sm.q.scnt[c][lane];
            int take = tot < 16 ? tot : 16;
            int emit = take == 0 ? 1 : take;
            int off = emit;
#pragma unroll
            for (int d = 1; d < 32; d <<= 1) {
                int v = __shfl_up_sync(0xffffffffu, off, d);
                if (lane >= d) off += v;
            }
            int total_emit = __shfl_sync(0xffffffffu, off, 31);
            int base_g = 0;
            if (lane == 31) base_g = atomicAdd(&g_scount, total_emit);
            base_g = __shfl_sync(0xffffffffu, base_g, 31);
            int mybase = base_g + off - emit;
            if (take == 0) {
                g_slist[mybase] = (g << 10);   // reference fill -> seed 0
            } else {
                int written = 0;
#pragma unroll
                for (int c = 0; c < 8; c++) {
                    int cc = sm.q.scnt[c][lane];
                    for (int i2v = 0; i2v < cc && written < take; i2v++) {
                        g_slist[mybase + written] = (g << 10) | (int)sm.q.sbuf[c][lane][i2v];
                        written++;
                    }
                }
            }
        }
    }
}

// ============================================================
// K3: persistent batched MLP over compacted samples (R7 form).
// W2 resident in smem. Tile = 32 samples. grid = 296 x 256
// ============================================================
__global__ void k3_gemm(const float* __restrict__ seed_xyz,
                        const float* __restrict__ W1,
                        const float* __restrict__ W2,
                        const float* __restrict__ b2,
                        const float* __restrict__ W3,
                        const float* __restrict__ b3) {
    __shared__ __align__(16) float W2s[H1][H2];   // 32 KB, [j][o]
    __shared__ float h1T[H1][33];   // [j][s]
    __shared__ float h2T[H2][33];   // [o][s]
    __shared__ float w1s[3][H1];
    __shared__ float sm_gx[32], sm_gy[32], sm_gz[32];
    __shared__ int   sm_f1[32], sm_pb[32];
    int t = threadIdx.x;
#pragma unroll
    for (int q = 0; q < 8; q++) {
        int fi = t + 256*q;
        ((float4*)W2s)[fi] = __ldg(&((const float4*)W2)[fi]);
    }
    if (t < 128) {
        w1s[0][t] = W1[t];
        w1s[1][t] = W1[128 + t];
        w1s[2][t] = W1[256 + t];
    }
    int count  = g_scount;
    int ntiles = (count + 31) >> 5;

    int s0 = t & 15, og = t >> 4, o0 = og * 4;
    float4 bb = __ldg((const float4*)&b2[o0]);

    for (int tile = blockIdx.x; tile < ntiles; tile += gridDim.x) {
        __syncthreads();
        if (t < 32) {
            int pos = tile*32 + t;
            if (pos >= count) pos = count - 1;   // dup: idempotent under max
            int e = g_slist[pos];
            int g = e >> 10, n = e & 1023;
            int b = g / KP_PER_B;
            int rem = g % KP_PER_B;
            int p = rem / KPP, kk = rem % KPP;
            sm_pb[t] = ((b*PP + p)*H3)*KPP + kk;
            int sidx = b*NN + n;
            sm_f1[t] = sidx;
            const float* sp = seed_xyz + (size_t)sidx*3;
            sm_gx[t] = (sp[0] - g_kpts[g*3+0]) * 5.0f;
            sm_gy[t] = (sp[1] - g_kpts[g*3+1]) * 5.0f;
            sm_gz[t] = (sp[2] - g_kpts[g*3+2]) * 5.0f;
        }
        __syncthreads();
        {
            int s = t >> 3, u = t & 7;
            const float* f1 = g_F1 + (size_t)sm_f1[s]*H1;
            float gx = sm_gx[s], gy = sm_gy[s], gz = sm_gz[s];
#pragma unroll
            for (int q = 0; q < 4; q++) {
                int j = u*16 + q*4;
                float4 f = __ldg((const float4*)&f1[j]);
                h1T[j+0][s] = fmaxf(f.x + gx*w1s[0][j+0] + gy*w1s[1][j+0] + gz*w1s[2][j+0], 0.f);
                h1T[j+1][s] = fmaxf(f.y + gx*w1s[0][j+1] + gy*w1s[1][j+1] + gz*w1s[2][j+1], 0.f);
                h1T[j+2][s] = fmaxf(f.z + gx*w1s[0][j+2] + gy*w1s[1][j+2] + gz*w1s[2][j+2], 0.f);
                h1T[j+3][s] = fmaxf(f.w + gx*w1s[0][j+3] + gy*w1s[1][j+3] + gz*w1s[2][j+3], 0.f);
            }
        }
        __syncthreads();
        float acc0[4] = {bb.x, bb.y, bb.z, bb.w};
        float acc1[4] = {bb.x, bb.y, bb.z, bb.w};
#pragma unroll 16
        for (int k = 0; k < H1; k++) {
            float a0 = h1T[k][s0];
            float a1 = h1T[k][s0 + 16];
            float4 wv = *(const float4*)&W2s[k][o0];
            acc0[0] = fmaf(a0, wv.x, acc0[0]); acc0[1] = fmaf(a0, wv.y, acc0[1]);
            acc0[2] = fmaf(a0, wv.z, acc0[2]); acc0[3] = fmaf(a0, wv.w, acc0[3]);
            acc1[0] = fmaf(a1, wv.x, acc1[0]); acc1[1] = fmaf(a1, wv.y, acc1[1]);
            acc1[2] = fmaf(a1, wv.z, acc1[2]); acc1[3] = fmaf(a1, wv.w, acc1[3]);
        }
#pragma unroll
        for (int q = 0; q < 4; q++) {
            h2T[o0+q][s0]      = fmaxf(acc0[q], 0.f);
            h2T[o0+q][s0 + 16] = fmaxf(acc1[q], 0.f);
        }
        __syncthreads();
        {
            int s = t & 31, cg = t >> 5;
            float4 b3v = __ldg((const float4*)&b3[cg*4]);
            float a0 = b3v.x, a1 = b3v.y, a2 = b3v.z, a3 = b3v.w;
#pragma unroll 16
            for (int k = 0; k < H2; k++) {
                float hv = h2T[k][s];
                float4 wv = __ldg((const float4*)&W3[(size_t)k*H3 + cg*4]);
                a0 = fmaf(hv, wv.x, a0); a1 = fmaf(hv, wv.y, a1);
                a2 = fmaf(hv, wv.z, a2); a3 = fmaf(hv, wv.w, a3);
            }
            int pb = sm_pb[s];
            int* pool = (int*)g_pool;
            atomicMax(&pool[pb + (cg*4+0)*KPP], __float_as_int(fmaxf(a0, 0.f)));
            atomicMax(&pool[pb + (cg*4+1)*KPP], __float_as_int(fmaxf(a1, 0.f)));
            atomicMax(&pool[pb + (cg*4+2)*KPP], __float_as_int(fmaxf(a2, 0.f)));
            atomicMax(&pool[pb + (cg*4+3)*KPP], __float_as_int(fmaxf(a3, 0.f)));
        }
    }
}

// ============================================================
// K4: out += pool @ Wr^T. 64x64 tiles, split-K=9 (96 k / block),
// register prefetch. grid = 144 x 256. Resets g_scount.
// ============================================================
__global__ void k4_final(const float* __restrict__ Wr,
                         float* __restrict__ out) {
    __shared__ __align__(16) float As[32][68];
    __shared__ __align__(16) float Bs[32][68];
    int t = threadIdx.x;
    if (blockIdx.x == 0 && t == 0) g_scount = 0;
    int tile = blockIdx.x & 15;
    int kc   = blockIdx.x >> 4;
    int r0 = (tile >> 1) * 64;
    int j0 = (tile & 1) * 64;
    int kb = kc * 96;
    int tr = t >> 4, tc = t & 15;
    float acc[4][4] = {};
    float ra[8], rb[8];

#pragma unroll
    for (int i = 0; i < 8; i++) {
        int e = t + 256*i; int kk = e & 31, rr = e >> 5;
        ra[i] = g_pool[(size_t)(r0+rr)*MTOT + kb + kk];
        rb[i] = Wr[(size_t)(j0+rr)*MTOT + kb + kk];
    }
#pragma unroll
    for (int c = 0; c < 3; c++) {
        __syncthreads();
#pragma unroll
        for (int i = 0; i < 8; i++) {
            int e = t + 256*i; int kk = e & 31, rr = e >> 5;
            As[kk][rr] = ra[i];
            Bs[kk][rr] = rb[i];
        }
        __syncthreads();
        if (c < 2) {
#pragma unroll
            for (int i = 0; i < 8; i++) {
                int e = t + 256*i; int kk = e & 31, rr = e >> 5;
                ra[i] = g_pool[(size_t)(r0+rr)*MTOT + kb + (c+1)*32 + kk];
                rb[i] = Wr[(size_t)(j0+rr)*MTOT + kb + (c+1)*32 + kk];
            }
        }
#pragma unroll
        for (int kk = 0; kk < 32; kk++) {
            float4 a = *(const float4*)&As[kk][tc*4];
            float4 w = *(const float4*)&Bs[kk][tr*4];
            float av[4] = {a.x,a.y,a.z,a.w};
            float wv[4] = {w.x,w.y,w.z,w.w};
#pragma unroll
            for (int r = 0; r < 4; r++)
#pragma unroll
                for (int q = 0; q < 4; q++) acc[r][q] += av[r]*wv[q];
        }
    }
#pragma unroll
    for (int r = 0; r < 4; r++) {
        int row = r0 + tc*4 + r;
        int b = row >> 8, p = row & 255;
#pragma unroll
        for (int q = 0; q < 4; q++) {
            int j = j0 + tr*4 + q;
            atomicAdd(&out[(size_t)b*H1*PP + (size_t)j*PP + p], acc[r][q]);
        }
    }
}

// ============================================================
extern "C" void kernel_launch(void* const* d_in, const int* in_sizes, int n_in,
                              void* d_out, int out_size) {
    const float* seed_xyz      = (const float*)d_in[0];
    const float* seed_features = (const float*)d_in[1];
    const float* boxes         = (const float*)d_in[2];
    const float* origins       = (const float*)d_in[3];
    const float* heading       = (const float*)d_in[4];
    const float* W1            = (const float*)d_in[5];
    const float* b1            = (const float*)d_in[6];
    const float* W2            = (const float*)d_in[7];
    const float* b2            = (const float*)d_in[8];
    const float* W3            = (const float*)d_in[9];
    const float* b3            = (const float*)d_in[10];
    const float* Wr            = (const float*)d_in[11];
    const float* br            = (const float*)d_in[12];
    float* out = (float*)d_out;

    k12_fused<<<K12_BLOCKS, 256>>>(seed_features, W1, b1,
                                   seed_xyz, boxes, origins, heading, br, out);
    k3_gemm<<<296, 256>>>(seed_xyz, W1, W2, b2, W3, b3);
    k4_final<<<144, 256>>>(Wr, out);
}